// round 6
// baseline (speedup 1.0000x reference)
#include <cuda_runtime.h>
#include <cstdint>
#include <cstddef>

#define B_ROWS 262144
#define TILE   32
#define NTILES (B_ROWS / TILE)   // 8192 CTAs
#define PAD    260               // padded row stride (floats); multiple of 4

// ---------- packed fp32x2 helpers (IEEE RN per lane; 2x FFMA rate on B300) ----
__device__ __forceinline__ unsigned long long pack2(float a, float b) {
    unsigned long long d;
    asm("mov.b64 %0, {%1, %2};" : "=l"(d) : "f"(a), "f"(b));
    return d;
}
__device__ __forceinline__ void unpack2(unsigned long long v, float& a, float& b) {
    asm("mov.b64 {%0, %1}, %2;" : "=f"(a), "=f"(b) : "l"(v));
}
__device__ __forceinline__ void ffma2(unsigned long long& d, unsigned long long a, unsigned long long b) {
    asm("fma.rn.f32x2 %0, %1, %2, %0;" : "+l"(d) : "l"(a), "l"(b));
}

// ---------------------------------------------------------------------------
// Diagnostic pre-pass: 5.0f everywhere. Overwritten by the compute kernel.
// If next rel_err ~= 0.157, the fill landed but compute did not.
// ---------------------------------------------------------------------------
__global__ void fill5(float* __restrict__ out, int n)
{
    int i = blockIdx.x * blockDim.x + threadIdx.x;
    int stride = gridDim.x * blockDim.x;
    for (; i < n; i += stride) out[i] = 5.0f;
}

// ---------------------------------------------------------------------------
// Fully fused actor MLP per CTA: state[32,128] -> h1[32,256] -> h2[32,256]
// -> out[32,8] (FLOAT32 output: values 1.0 .. 9.0).
// Final step replicates XLA fp32 semantics: logistic -> 0.5+0.5*tanh(x/2),
// tanh linear near 0; exact fp32 crossover for the decisive 4/5 boundary:
//   out >= 5  <=>  v > -3*2^-24  (== -0x1.8p-23)
// ---------------------------------------------------------------------------
__global__ void __launch_bounds__(256)
actor_fused(const float* __restrict__ state,
            const float* __restrict__ W1, const float* __restrict__ b1,
            const float* __restrict__ W2, const float* __restrict__ b2,
            const float* __restrict__ W3, const float* __restrict__ b3,
            const float* __restrict__ eps, float* __restrict__ out)
{
    __shared__ __align__(16) float buf[TILE * PAD];  // 33,280 B: state -> h1 -> h2
    __shared__ __align__(16) float Wc [8 * PAD];     // 8,320 B: streamed weight chunk

    const int tid = threadIdx.x;
    const int t   = blockIdx.x;
    const int tx  = tid & 31;        // col pair index within warp
    const int ty  = tid >> 5;        // warp id: owns rows 4*ty .. 4*ty+3

    // ---- load state tile [32][128] into buf ----
    {
        const float4* s4 = (const float4*)(state + (size_t)t * TILE * 128);
        #pragma unroll
        for (int j = 0; j < 4; ++j) {
            int idx = tid + j * 256;          // 0..1023 (32 rows x 32 float4)
            int r = idx >> 5, c4 = idx & 31;
            *(float4*)&buf[r * PAD + c4 * 4] = s4[idx];
        }
    }

    unsigned long long acc[4][4];    // 4 rows x 4 column-pairs (8 cols)

    // ================= phase 1: h1 = relu(state @ W1^T + b1), K=128 ============
    #pragma unroll
    for (int i = 0; i < 4; ++i)
        #pragma unroll
        for (int m = 0; m < 4; ++m) acc[i][m] = 0ull;

    for (int kc = 0; kc < 128; kc += 8) {
        __syncthreads();   // prior Wc readers done (kc==0: state tile visible)
        #pragma unroll
        for (int j = 0; j < 2; ++j) {
            int idx = tid + j * 256;          // 0..511
            int n = idx >> 1, q = idx & 1;
            float4 w = *(const float4*)(W1 + n * 128 + kc + q * 4);
            Wc[(q * 4 + 0) * PAD + n] = w.x;
            Wc[(q * 4 + 1) * PAD + n] = w.y;
            Wc[(q * 4 + 2) * PAD + n] = w.z;
            Wc[(q * 4 + 3) * PAD + n] = w.w;
        }
        __syncthreads();
        #pragma unroll
        for (int kk = 0; kk < 8; ++kk) {
            unsigned long long ap[4];
            #pragma unroll
            for (int i = 0; i < 4; ++i) {
                float a = buf[(4 * ty + i) * PAD + kc + kk];
                ap[i] = pack2(a, a);
            }
            unsigned long long bp[4];
            #pragma unroll
            for (int m = 0; m < 4; ++m)
                bp[m] = *(const unsigned long long*)&Wc[kk * PAD + 2 * tx + 64 * m];
            #pragma unroll
            for (int i = 0; i < 4; ++i)
                #pragma unroll
                for (int m = 0; m < 4; ++m)
                    ffma2(acc[i][m], ap[i], bp[m]);
        }
    }
    __syncthreads();       // all phase-1 reads of buf complete before overwrite
    #pragma unroll
    for (int i = 0; i < 4; ++i)
        #pragma unroll
        for (int m = 0; m < 4; ++m) {
            int n = 2 * tx + 64 * m;
            float lo, hi;
            unpack2(acc[i][m], lo, hi);
            lo = fmaxf(lo + b1[n],     0.f);
            hi = fmaxf(hi + b1[n + 1], 0.f);
            *(float2*)&buf[(4 * ty + i) * PAD + n] = make_float2(lo, hi);
        }

    // ================= phase 2: h2 = relu(h1 @ W2^T + b2), K=256 ===============
    #pragma unroll
    for (int i = 0; i < 4; ++i)
        #pragma unroll
        for (int m = 0; m < 4; ++m) acc[i][m] = 0ull;

    for (int kc = 0; kc < 256; kc += 8) {
        __syncthreads();   // h1 writes (kc==0) / prior Wc readers done
        #pragma unroll
        for (int j = 0; j < 2; ++j) {
            int idx = tid + j * 256;
            int n = idx >> 1, q = idx & 1;
            float4 w = *(const float4*)(W2 + n * 256 + kc + q * 4);
            Wc[(q * 4 + 0) * PAD + n] = w.x;
            Wc[(q * 4 + 1) * PAD + n] = w.y;
            Wc[(q * 4 + 2) * PAD + n] = w.z;
            Wc[(q * 4 + 3) * PAD + n] = w.w;
        }
        __syncthreads();
        #pragma unroll
        for (int kk = 0; kk < 8; ++kk) {
            unsigned long long ap[4];
            #pragma unroll
            for (int i = 0; i < 4; ++i) {
                float a = buf[(4 * ty + i) * PAD + kc + kk];
                ap[i] = pack2(a, a);
            }
            unsigned long long bp[4];
            #pragma unroll
            for (int m = 0; m < 4; ++m)
                bp[m] = *(const unsigned long long*)&Wc[kk * PAD + 2 * tx + 64 * m];
            #pragma unroll
            for (int i = 0; i < 4; ++i)
                #pragma unroll
                for (int m = 0; m < 4; ++m)
                    ffma2(acc[i][m], ap[i], bp[m]);
        }
    }
    __syncthreads();       // all phase-2 reads of buf complete
    #pragma unroll
    for (int i = 0; i < 4; ++i)
        #pragma unroll
        for (int m = 0; m < 4; ++m) {
            int n = 2 * tx + 64 * m;
            float lo, hi;
            unpack2(acc[i][m], lo, hi);
            lo = fmaxf(lo + b2[n],     0.f);
            hi = fmaxf(hi + b2[n + 1], 0.f);
            *(float2*)&buf[(4 * ty + i) * PAD + n] = make_float2(lo, hi);
        }
    __syncthreads();       // h2 visible to all

    // ================= phase 3: head ==========================================
    const int r  = tid >> 3;     // row 0..31
    const int jj = tid & 7;      // output column 0..7
    float d2[2];

    #pragma unroll
    for (int half = 0; half < 2; ++half) {
        // stage W3 rows [half*8, half*8+8) transposed: Wc[k*8 + j]
        #pragma unroll
        for (int j = 0; j < 2; ++j) {
            int idx = tid + j * 256;          // 0..511 (8 rows x 64 float4)
            int jr = idx >> 6, k4 = idx & 63;
            float4 w = *(const float4*)(W3 + (size_t)(half * 8 + jr) * 256 + k4 * 4);
            Wc[(k4 * 4 + 0) * 8 + jr] = w.x;
            Wc[(k4 * 4 + 1) * 8 + jr] = w.y;
            Wc[(k4 * 4 + 2) * 8 + jr] = w.z;
            Wc[(k4 * 4 + 3) * 8 + jr] = w.w;
        }
        __syncthreads();
        float d = 0.f;
        #pragma unroll 8
        for (int k = 0; k < 256; ++k)
            d = fmaf(buf[r * PAD + k], Wc[k * 8 + jj], d);
        d2[half] = d;
        __syncthreads();   // dot done before Wc is restaged
    }

    float u = d2[0] + b3[jj];
    float s = fabsf(d2[1] + b3[jj + 8]);
    float e = eps[((size_t)t * TILE + r) * 8 + jj];
    float v = fmaf(s, e, u);     // XLA fuses the mul+add

    // out = 1 + #(thresholds strictly below v); decisive 4/5 boundary exact.
    int o = 1;
    o += (v > -1.9459101f);
    o += (v > -1.0986123f);
    o += (v > -0.51082563f);
    o += (v > -0x1.8p-23f);      // == -3*2^-24, exact fp32 crossover of sigmoid=0.5
    o += (v >  0.51082563f);
    o += (v >  1.0986123f);
    o += (v >  1.9459101f);
    out[((size_t)t * TILE + r) * 8 + jj] = (float)o;   // FLOAT32 output
}

// ============================================================================
extern "C" void kernel_launch(void* const* d_in, const int* in_sizes, int n_in,
                              void* d_out, int out_size)
{
    const float* state = nullptr; const float* W1 = nullptr; const float* b1 = nullptr;
    const float* W2 = nullptr;    const float* b2 = nullptr; const float* W3 = nullptr;
    const float* b3 = nullptr;    const float* eps = nullptr;

    // Pass 0: element counts. Pass 1: byte counts.
    for (int pass = 0; pass < 2 && !state; ++pass) {
        long long mul = (pass == 0) ? 1 : 4;
        state = W1 = b1 = W2 = b2 = W3 = b3 = eps = nullptr;
        for (int i = 0; i < n_in; ++i) {
            const float* p = (const float*)d_in[i];
            long long sz = (long long)in_sizes[i];
            if      (sz == 33554432LL * mul) state = p;
            else if (sz == 32768LL    * mul) W1 = p;
            else if (sz == 65536LL    * mul) W2 = p;
            else if (sz == 4096LL     * mul) W3 = p;
            else if (sz == 2097152LL  * mul) eps = p;
            else if (sz == 16LL       * mul) b3 = p;
            else if (sz == 256LL      * mul) { if (!b1) b1 = p; else b2 = p; }
        }
    }
    // Positional fallback: reference insertion order.
    if (!state || !W1 || !b1 || !W2 || !b2 || !W3 || !b3 || !eps) {
        state = (const float*)d_in[0]; W1 = (const float*)d_in[1];
        b1    = (const float*)d_in[2]; W2 = (const float*)d_in[3];
        b2    = (const float*)d_in[4]; W3 = (const float*)d_in[5];
        b3    = (const float*)d_in[6]; eps = (const float*)d_in[7];
    }
    float* out = (float*)d_out;

    // Diagnostic pre-fill (overwritten by the compute kernel if it runs).
    fill5<<<1024, 256>>>(out, out_size);
    // Full fused pipeline.
    actor_fused<<<NTILES, 256>>>(state, W1, b1, W2, b2, W3, b3, eps, out);
}

// round 7
// speedup vs baseline: 1.3594x; 1.3594x over previous
#include <cuda_runtime.h>
#include <cstdint>
#include <cstddef>

#define B_ROWS 262144
#define TILE_R 64
#define NT     (B_ROWS / TILE_R)   // 4096 CTAs
#define PAD    260                 // padded row stride (floats), multiple of 4
#define CH     16                  // k-chunk staged in smem

// dynamic smem layout: buf[64*PAD] | Ws[CH*PAD]
#define SMEM_BUF_FLOATS (TILE_R * PAD)
#define SMEM_WS_FLOATS  (CH * PAD)
#define SMEM_TOTAL      ((SMEM_BUF_FLOATS + SMEM_WS_FLOATS) * 4)   // 83,200 B

// ---------- packed fp32x2 helpers (IEEE RN per lane; 2x FFMA rate) ----------
__device__ __forceinline__ unsigned long long pack2(float a, float b) {
    unsigned long long d;
    asm("mov.b64 %0, {%1, %2};" : "=l"(d) : "f"(a), "f"(b));
    return d;
}
__device__ __forceinline__ void unpack2(unsigned long long v, float& a, float& b) {
    asm("mov.b64 {%0, %1}, %2;" : "=f"(a), "=f"(b) : "l"(v));
}
__device__ __forceinline__ void ffma2(unsigned long long& d, unsigned long long a, unsigned long long b) {
    asm("fma.rn.f32x2 %0, %1, %2, %0;" : "+l"(d) : "l"(a), "l"(b));
}

// ---------------------------------------------------------------------------
// One GEMM phase: buf[:, 0:256] = relu( buf[:, 0:K] @ W^T + bias ), in place.
// Thread tile: 4 rows (4*ty..4*ty+3) x 16 cols (4*tx+64g, g=0..3).
// K-chunks of CH staged transposed in Ws. Accumulation order: k ascending
// (bit-identical to the round-6 passing kernel).
// ---------------------------------------------------------------------------
template<int K>
__device__ __forceinline__ void gemm_phase(const float* __restrict__ W,
                                           const float* __restrict__ bias,
                                           float* __restrict__ buf,
                                           float* __restrict__ Ws,
                                           int tid, int tx, int ty)
{
    unsigned long long acc[4][8];
    #pragma unroll
    for (int i = 0; i < 4; ++i)
        #pragma unroll
        for (int m = 0; m < 8; ++m) acc[i][m] = 0ull;

    for (int kc = 0; kc < K; kc += CH) {
        __syncthreads();   // prior readers of Ws done (first chunk: buf staging visible)
        // stage Ws[kk][n] = W[n][kc+kk]  (256 n x 4 float4 along k)
        #pragma unroll
        for (int j = 0; j < 4; ++j) {
            int idx = tid + j * 256;          // 0..1023
            int n  = idx >> 2;
            int f4 = idx & 3;
            float4 w = *(const float4*)(W + (size_t)n * K + kc + f4 * 4);
            Ws[(f4 * 4 + 0) * PAD + n] = w.x;
            Ws[(f4 * 4 + 1) * PAD + n] = w.y;
            Ws[(f4 * 4 + 2) * PAD + n] = w.z;
            Ws[(f4 * 4 + 3) * PAD + n] = w.w;
        }
        __syncthreads();

        #pragma unroll
        for (int kk4 = 0; kk4 < CH / 4; ++kk4) {
            float4 av[4];
            #pragma unroll
            for (int i = 0; i < 4; ++i)
                av[i] = *(const float4*)&buf[(4 * ty + i) * PAD + kc + kk4 * 4];
            #pragma unroll
            for (int kx = 0; kx < 4; ++kx) {
                int krow = kk4 * 4 + kx;
                unsigned long long bp[8];
                #pragma unroll
                for (int g = 0; g < 4; ++g) {
                    float4 w = *(const float4*)&Ws[krow * PAD + 4 * tx + 64 * g];
                    bp[2 * g]     = pack2(w.x, w.y);
                    bp[2 * g + 1] = pack2(w.z, w.w);
                }
                #pragma unroll
                for (int i = 0; i < 4; ++i) {
                    float a = (kx == 0) ? av[i].x : (kx == 1) ? av[i].y
                            : (kx == 2) ? av[i].z : av[i].w;
                    unsigned long long ap = pack2(a, a);
                    #pragma unroll
                    for (int m = 0; m < 8; ++m) ffma2(acc[i][m], ap, bp[m]);
                }
            }
        }
    }

    // epilogue: bias + relu, float4 stores, in place (rows are warp-private).
    #pragma unroll
    for (int i = 0; i < 4; ++i) {
        #pragma unroll
        for (int g = 0; g < 4; ++g) {
            int n0 = 4 * tx + 64 * g;
            float4 r4;
            unpack2(acc[i][2 * g],     r4.x, r4.y);
            unpack2(acc[i][2 * g + 1], r4.z, r4.w);
            float4 bb = *(const float4*)(bias + n0);
            r4.x = fmaxf(r4.x + bb.x, 0.f);
            r4.y = fmaxf(r4.y + bb.y, 0.f);
            r4.z = fmaxf(r4.z + bb.z, 0.f);
            r4.w = fmaxf(r4.w + bb.w, 0.f);
            *(float4*)&buf[(4 * ty + i) * PAD + n0] = r4;
        }
    }
}

// ---------------------------------------------------------------------------
// Fully fused actor MLP per CTA: state[64,128] -> h1[64,256] -> h2[64,256]
// -> out[64,8] (float32 values 1.0 .. 9.0).
// Head replicates XLA fp32 logistic semantics; decisive 4/5 boundary:
//   out >= 5  <=>  v > -3*2^-24  (== -0x1.8p-23), verified rel_err = 0.0.
// ---------------------------------------------------------------------------
__global__ void __launch_bounds__(256, 2)
actor_fused(const float* __restrict__ state,
            const float* __restrict__ W1, const float* __restrict__ b1,
            const float* __restrict__ W2, const float* __restrict__ b2,
            const float* __restrict__ W3, const float* __restrict__ b3,
            const float* __restrict__ eps, float* __restrict__ out)
{
    extern __shared__ __align__(16) float smem[];
    float* buf = smem;                      // [64][PAD]
    float* Ws  = smem + SMEM_BUF_FLOATS;    // [CH][PAD]  (also holds W3 for head)

    const int tid = threadIdx.x;
    const int t   = blockIdx.x;
    const int tx  = tid & 15;     // 16 col groups
    const int ty  = tid >> 4;     // 16 row groups of 4 rows

    // ---- load state tile [64][128] into buf ----
    {
        const float4* s4 = (const float4*)(state + (size_t)t * TILE_R * 128);
        #pragma unroll
        for (int j = 0; j < 8; ++j) {
            int idx = tid + j * 256;          // 0..2047 (64 rows x 32 float4)
            int r = idx >> 5, c4 = idx & 31;
            *(float4*)&buf[r * PAD + c4 * 4] = s4[idx];
        }
    }

    // phase 1: h1 = relu(state @ W1^T + b1), K=128
    gemm_phase<128>(W1, b1, buf, Ws, tid, tx, ty);
    // phase 2: h2 = relu(h1 @ W2^T + b2), K=256 (in place)
    gemm_phase<256>(W2, b2, buf, Ws, tid, tx, ty);

    // ================= head =================
    __syncthreads();   // all phase-2 Ws reads done; buf (h2) writes visible after next sync
    // stage W3 [16][256] straight into Ws rows (no transpose): Ws[j*PAD + k]
    #pragma unroll
    for (int j = 0; j < 4; ++j) {
        int idx = tid + j * 256;              // 0..1023 (16 rows x 64 float4)
        int jr = idx >> 6, k4 = idx & 63;
        *(float4*)&Ws[jr * PAD + k4 * 4] = *(const float4*)(W3 + (size_t)jr * 256 + k4 * 4);
    }
    __syncthreads();

    const int r = tid >> 2;      // row 0..63
    const int q = tid & 3;       // handles output cols q, q+4 (u) / q+8, q+12 (s)

    float d[4] = {0.f, 0.f, 0.f, 0.f};   // dots for jj = q, q+4, q+8, q+12
    #pragma unroll 8
    for (int k4 = 0; k4 < 64; ++k4) {
        float4 h = *(const float4*)&buf[r * PAD + k4 * 4];
        #pragma unroll
        for (int c = 0; c < 4; ++c) {
            int jj = q + 4 * c;
            float4 w = *(const float4*)&Ws[jj * PAD + k4 * 4];
            d[c] = fmaf(h.x, w.x, d[c]);
            d[c] = fmaf(h.y, w.y, d[c]);
            d[c] = fmaf(h.z, w.z, d[c]);
            d[c] = fmaf(h.w, w.w, d[c]);
        }
    }

    const size_t row = (size_t)t * TILE_R + r;
    float u0 = d[0] + b3[q];
    float u1 = d[1] + b3[q + 4];
    float s0 = fabsf(d[2] + b3[q + 8]);
    float s1 = fabsf(d[3] + b3[q + 12]);
    float e0 = eps[row * 8 + q];
    float e1 = eps[row * 8 + q + 4];
    float v0 = fmaf(s0, e0, u0);
    float v1 = fmaf(s1, e1, u1);

    #pragma unroll
    for (int half = 0; half < 2; ++half) {
        float v = half ? v1 : v0;
        int o = 1;
        o += (v > -1.9459101f);
        o += (v > -1.0986123f);
        o += (v > -0.51082563f);
        o += (v > -0x1.8p-23f);      // exact fp32 crossover of sigmoid==0.5
        o += (v >  0.51082563f);
        o += (v >  1.0986123f);
        o += (v >  1.9459101f);
        out[row * 8 + q + 4 * half] = (float)o;
    }
}

// ============================================================================
extern "C" void kernel_launch(void* const* d_in, const int* in_sizes, int n_in,
                              void* d_out, int out_size)
{
    const float* state = nullptr; const float* W1 = nullptr; const float* b1 = nullptr;
    const float* W2 = nullptr;    const float* b2 = nullptr; const float* W3 = nullptr;
    const float* b3 = nullptr;    const float* eps = nullptr;

    for (int pass = 0; pass < 2 && !state; ++pass) {
        long long mul = (pass == 0) ? 1 : 4;
        state = W1 = b1 = W2 = b2 = W3 = b3 = eps = nullptr;
        for (int i = 0; i < n_in; ++i) {
            const float* p = (const float*)d_in[i];
            long long sz = (long long)in_sizes[i];
            if      (sz == 33554432LL * mul) state = p;
            else if (sz == 32768LL    * mul) W1 = p;
            else if (sz == 65536LL    * mul) W2 = p;
            else if (sz == 4096LL     * mul) W3 = p;
            else if (sz == 2097152LL  * mul) eps = p;
            else if (sz == 16LL       * mul) b3 = p;
            else if (sz == 256LL      * mul) { if (!b1) b1 = p; else b2 = p; }
        }
    }
    if (!state || !W1 || !b1 || !W2 || !b2 || !W3 || !b3 || !eps) {
        state = (const float*)d_in[0]; W1 = (const float*)d_in[1];
        b1    = (const float*)d_in[2]; W2 = (const float*)d_in[3];
        b2    = (const float*)d_in[4]; W3 = (const float*)d_in[5];
        b3    = (const float*)d_in[6]; eps = (const float*)d_in[7];
    }

    static bool attr_done = false;
    if (!attr_done) {
        cudaFuncSetAttribute(actor_fused,
                             cudaFuncAttributeMaxDynamicSharedMemorySize, SMEM_TOTAL);
        attr_done = true;
    }

    actor_fused<<<NT, 256, SMEM_TOTAL>>>(state, W1, b1, W2, b2, W3, b3, eps,
                                         (float*)d_out);
}